// round 11
// baseline (speedup 1.0000x reference)
#include <cuda_runtime.h>
#include <math.h>
#include <stdint.h>

// ---------------------------------------------------------------------------
// SVM RBF inference: out = tanh(K @ (labels*relu(lambda)) + b)
//   K[b,n] = exp(-(||x_b||^2+||s_n||^2-2 x_b.s_n)/2), B=2048, N=50000, D=256
// v10: INT8 IMMA screening. Cross-round evidence (R1/R5/R9/R10) fits
//   cost ~ (#PTX mma.sync) x ~16 SMSP-cycles, independent of occupancy and
//   tile shape. k32 s8 IMMA halves the PTX MMA count for the same 64-wide
//   screen. Quantize q = clamp(round(16*x)); dims 0..61 data, dims 62/63
//   encode norms via +-127*round(||q||^2/254), so
//     acc = IP - X2/2 - S2/2 (+-128) = -Qi/2 (+-128),
//   Qi = 256 * ||xhat - shat||^2_62 EXACT in int32 (quantized vectors).
//   Skip when acc < -7600  =>  true d^2_62 >= 51.1 (after +-0.49 quant and
//   +-0.5 aug margins); skipped mass < 2e-11 vs tol 7.6e-4. Rescans
//   (P~1.8e-4/elem) take the exact fp32 256-dim fixup from ORIGINAL inputs.
//   Norm-encoding saturation only increases rescans (safe direction).
//   Epilogue screen: IMNMX tree + 1 compare per 16 accs. tanh finalize
//   folded into last-arriving CTA.
// ---------------------------------------------------------------------------

#define B_ROWS   2048
#define D_DIM    256
#define D_H      64              // screening bytes (62 data dims + 2 aug)
#define N_ROWS   50000
#define N_PAD    50176           // 392 * 128
#define N_TILES  392
#define BM       128
#define BN       128
#define THREADS  256
#define NSPLIT   18
#define GRID_X   (B_ROWS / BM)   // 16
#define TOTAL_CTAS (GRID_X * NSPLIT)   // 288 = one wave at 2 CTA/SM
#define TACCI    (-7600)         // rescan if acc >= TACCI

#define STRIDE   80              // 64 B data + 16 pad (5*16B: LDSM conflict-free)
#define A_BYTES  (BM * STRIDE)   // 10240
#define B_STG    (BN * STRIDE)   // 10240
#define NSTG     3
#define SMEM_BYTES (A_BYTES + NSTG * B_STG) // 40960

// Scratch (static device arrays: no allocation anywhere)
__device__ __align__(256) int8_t g_xs[B_ROWS * D_H];
__device__ __align__(256) int8_t g_ss[N_PAD * D_H];
__device__ __align__(256) float  g_w[N_PAD];
__device__ __align__(256) float  g_acc[B_ROWS];
__device__ int g_done;           // 0 at start of every call (self-resetting)

// ---------------------------------------------------------------------------
// Prep: one warp per row. Lanes 0..30 quantize dims 0..61; lane 31 writes the
// two norm-encoding bytes. Warp-reduced X2 = sum(q^2) over the 62 data dims.
// ---------------------------------------------------------------------------
__device__ __forceinline__ int q8(float v) {
    int q = __float2int_rn(16.0f * v);
    return max(-127, min(127, q));
}
__device__ __forceinline__ short pack2(int q0, int q1) {
    return (short)((q0 & 0xFF) | ((q1 & 0xFF) << 8));
}

__global__ void prep(const float* __restrict__ x,
                     const float* __restrict__ ds,
                     const float* __restrict__ labels,
                     const float* __restrict__ lam) {
    const int lane = threadIdx.x & 31;
    const int gw = blockIdx.x * 8 + (threadIdx.x >> 5);
    if (gw < B_ROWS) {
        const int row = gw;
        float2 v = reinterpret_cast<const float2*>(x + (size_t)row * D_DIM)[lane];
        int q0 = q8(v.x), q1 = q8(v.y);
        int ss = (lane < 31) ? (q0 * q0 + q1 * q1) : 0;
        #pragma unroll
        for (int o = 16; o > 0; o >>= 1) ss += __shfl_xor_sync(0xffffffffu, ss, o);
        short* dst = reinterpret_cast<short*>(g_xs + (size_t)row * D_H);
        if (lane < 31) dst[lane] = pack2(q0, q1);
        else {
            int xa = min(127, (ss + 127) / 254);
            dst[31] = pack2(xa, -127);      // dim62 = xa (s side -127), dim63 = -127
        }
        if (lane == 0) g_acc[row] = 0.0f;
    } else {
        const int row = gw - B_ROWS;
        if (row >= N_PAD) return;
        short* dst = reinterpret_cast<short*>(g_ss + (size_t)row * D_H);
        if (row < N_ROWS) {
            float2 v = reinterpret_cast<const float2*>(ds + (size_t)row * D_DIM)[lane];
            int q0 = q8(v.x), q1 = q8(v.y);
            int ss = (lane < 31) ? (q0 * q0 + q1 * q1) : 0;
            #pragma unroll
            for (int o = 16; o > 0; o >>= 1) ss += __shfl_xor_sync(0xffffffffu, ss, o);
            if (lane < 31) dst[lane] = pack2(q0, q1);
            else {
                int sa = min(127, (ss + 127) / 254);
                dst[31] = pack2(-127, sa);  // dim62 = -127 (x side xa), dim63 = sa
            }
            if (lane == 0) g_w[row] = labels[row] * fmaxf(lam[row], 0.0f);
        } else {
            if (lane < 31) dst[lane] = 0;
            else dst[31] = pack2(-127, 127);   // acc <= -16129: always skipped
            if (lane == 0) g_w[row] = 0.0f;
        }
    }
}

// ---------------------------------------------------------------------------
// PTX helpers
// ---------------------------------------------------------------------------
__device__ __forceinline__ void cp16(uint32_t saddr, const void* gaddr) {
    asm volatile("cp.async.cg.shared.global [%0], [%1], 16;\n"
                 :: "r"(saddr), "l"(gaddr));
}
__device__ __forceinline__ void cp_commit() {
    asm volatile("cp.async.commit_group;\n");
}
template <int N>
__device__ __forceinline__ void cp_wait() {
    asm volatile("cp.async.wait_group %0;\n" :: "n"(N));
}
__device__ __forceinline__ void ldsm4(uint32_t* r, uint32_t addr) {
    asm volatile("ldmatrix.sync.aligned.m8n8.x4.shared.b16 {%0,%1,%2,%3}, [%4];"
                 : "=r"(r[0]), "=r"(r[1]), "=r"(r[2]), "=r"(r[3]) : "r"(addr));
}
__device__ __forceinline__ void mma_s8(int* d, const uint32_t a[4],
                                       uint32_t b0, uint32_t b1) {
    asm volatile(
        "mma.sync.aligned.m16n8k32.row.col.s32.s8.s8.s32 "
        "{%0,%1,%2,%3},{%4,%5,%6,%7},{%8,%9},{%0,%1,%2,%3};"
        : "+r"(d[0]), "+r"(d[1]), "+r"(d[2]), "+r"(d[3])
        : "r"(a[0]), "r"(a[1]), "r"(a[2]), "r"(a[3]), "r"(b0), "r"(b1));
}

// Cold path: exact 256-dim fp32 squared distance from the ORIGINAL inputs.
__device__ __noinline__ float exact_sqdist(const float* __restrict__ xr,
                                           const float* __restrict__ sr) {
    float d2 = 0.0f;
    #pragma unroll 1
    for (int i = 0; i < D_DIM / 4; i++) {
        float4 a = reinterpret_cast<const float4*>(xr)[i];
        float4 b = reinterpret_cast<const float4*>(sr)[i];
        float dx = a.x - b.x, dy = a.y - b.y, dz = a.z - b.z, dw = a.w - b.w;
        d2 += dx * dx + dy * dy + dz * dz + dw * dw;
    }
    return d2;
}

// ---------------------------------------------------------------------------
// Main fused kernel (IMMA screen + cold exact fixup + folded tanh finalize)
//   8 warps: wm = wid&3 (M, 32 rows), wn = wid>>2 (N, 64 cols)
// s32 acc register layout (m16n8k32): reg r of lane l =
//   row = (l>>2) + 8*(r>>1),  col = 2*(l&3) + (r&1)
// ---------------------------------------------------------------------------
__global__ void __launch_bounds__(THREADS, 2)
svm_main(const float* __restrict__ xp, const float* __restrict__ sp,
         const float* __restrict__ bb, float* __restrict__ out) {
    extern __shared__ char smem[];
    uint32_t smem_u;
    asm("{ .reg .u64 t; cvta.to.shared.u64 t, %1; cvt.u32.u64 %0, t; }"
        : "=r"(smem_u) : "l"(smem));
    const uint32_t sA = smem_u;
    const uint32_t sB = smem_u + A_BYTES;

    const int tid  = threadIdx.x;
    const int lane = tid & 31;
    const int wid  = tid >> 5;
    const int wm   = wid & 3;   // 4 warps along M (32 rows each)
    const int wn   = wid >> 2;  // 2 warps along N (64 cols each)
    const int bm0  = blockIdx.x * BM;
    const int split = blockIdx.y;

    // ---- A tile load (128 rows x 64 s8), resident ----
    {
        const int8_t* gx = g_xs + (size_t)bm0 * D_H;
        #pragma unroll
        for (int i = 0; i < 2; i++) {
            int u = tid + THREADS * i;      // 0..511 16B chunks
            int r = u >> 2, c = u & 3;
            cp16(sA + r * STRIDE + c * 16, gx + (size_t)r * D_H + c * 16);
        }
        cp_commit();                        // GA
    }

    auto load_b = [&](int buf, int t0) {
        const int8_t* gs = g_ss + (size_t)t0 * BN * D_H;
        const uint32_t base = sB + buf * B_STG;
        #pragma unroll
        for (int i = 0; i < 2; i++) {
            int u = tid + THREADS * i;
            int r = u >> 2, c = u & 3;
            cp16(base + r * STRIDE + c * 16, gs + (size_t)r * D_H + c * 16);
        }
    };

    const int ntiles = (N_TILES - split + NSPLIT - 1) / NSPLIT;
    load_b(0, split); cp_commit();          // G0
    if (ntiles > 1) load_b(1, split + NSPLIT);
    cp_commit();                            // G1 (possibly empty)

    // ---- hoisted LDSM addresses ----
    uint32_t a_base[2];
    #pragma unroll
    for (int mi = 0; mi < 2; mi++) {
        int r = wm * 32 + mi * 16 + (lane & 15);
        a_base[mi] = sA + r * STRIDE + (lane >> 4) * 16;
    }
    uint32_t b_row[4];
    {
        int grp = lane >> 3;
        #pragma unroll
        for (int p = 0; p < 4; p++) {
            int r = wn * 64 + p * 16 + (grp >> 1) * 8 + (lane & 7);
            b_row[p] = (uint32_t)(r * STRIDE + (grp & 1) * 16);
        }
    }

    float rsum[2][2] = {{0.0f, 0.0f}, {0.0f, 0.0f}};

    int t = split;
    for (int ti = 0; ti < ntiles; ti++, t += NSPLIT) {
        cp_wait<1>();            // tile ti's group complete (ti+1 in flight)
        __syncthreads();         // single barrier: also protects stage (ti+2)%3
                                 // (last read at tile ti-1) before refill below

        if (ti + 2 < ntiles) load_b((ti + 2) % NSTG, t + 2 * NSPLIT);
        cp_commit();             // always commit (keeps wait<1> exact)

        const uint32_t stg = sB + (ti % NSTG) * B_STG;

        int acc[2][8][4];
        #pragma unroll
        for (int mi = 0; mi < 2; mi++)
            #pragma unroll
            for (int ni = 0; ni < 8; ni++)
                #pragma unroll
                for (int r = 0; r < 4; r++) acc[mi][ni][r] = 0;

        #pragma unroll
        for (int j = 0; j < 2; j++) {        // 2 k32 steps over D_H=64
            // batch 6 independent LDSMs (2 A + 4 B) -> MLP 6 (R5-proven)
            uint32_t a[2][4], bq[4][4];
            ldsm4(a[0], a_base[0] + j * 32);
            ldsm4(a[1], a_base[1] + j * 32);
            #pragma unroll
            for (int p = 0; p < 4; p++)
                ldsm4(bq[p], stg + b_row[p] + j * 32);
            // 16 IMMAs
            #pragma unroll
            for (int p = 0; p < 4; p++) {
                mma_s8(acc[0][2 * p],     a[0], bq[p][0], bq[p][1]);
                mma_s8(acc[0][2 * p + 1], a[0], bq[p][2], bq[p][3]);
                mma_s8(acc[1][2 * p],     a[1], bq[p][0], bq[p][1]);
                mma_s8(acc[1][2 * p + 1], a[1], bq[p][2], bq[p][3]);
            }
        }

        // ---- epilogue: acc == -Qi/2 (+-128); IMNMX screen, cold fixup ----
        const int n0 = t * BN;
        #pragma unroll
        for (int mi = 0; mi < 2; mi++) {
            #pragma unroll
            for (int h = 0; h < 2; h++) {
                const int h2 = 2 * h;
                int mx = acc[mi][0][h2];
                #pragma unroll
                for (int ni = 0; ni < 8; ni++) {
                    mx = max(mx, acc[mi][ni][h2]);
                    mx = max(mx, acc[mi][ni][h2 + 1]);
                }
                if (__builtin_expect(mx >= TACCI, 0)) {
                    const int row = bm0 + wm * 32 + mi * 16 + (lane >> 2) + 8 * h;
                    const float* xr = xp + (size_t)row * D_DIM;
                    #pragma unroll
                    for (int ni = 0; ni < 8; ni++) {
                        #pragma unroll
                        for (int par = 0; par < 2; par++) {
                            int v = acc[mi][ni][h2 + par];
                            const int col = n0 + wn * 64 + ni * 8 + 2 * (lane & 3) + par;
                            if (v >= TACCI && col < N_ROWS) {
                                float d2 = exact_sqdist(xr, sp + (size_t)col * D_DIM);
                                rsum[mi][h] += __expf(-0.5f * d2) * g_w[col];
                            }
                        }
                    }
                }
            }
        }
    }

    // ---- row reduction: shfl within quad, one atomic per row per CTA ----
    #pragma unroll
    for (int mi = 0; mi < 2; mi++) {
        #pragma unroll
        for (int h = 0; h < 2; h++) {
            float v = rsum[mi][h];
            v += __shfl_xor_sync(0xffffffffu, v, 1);
            v += __shfl_xor_sync(0xffffffffu, v, 2);
            if ((lane & 3) == 0) {
                int r = bm0 + wm * 32 + mi * 16 + (lane >> 2) + h * 8;
                atomicAdd(&g_acc[r], v);
            }
        }
    }

    // ---- folded finalize: last CTA applies tanh(acc + b) ----
    __shared__ int s_last;
    __threadfence();
    __syncthreads();
    if (tid == 0) {
        int old = atomicAdd(&g_done, 1);
        s_last = (old == TOTAL_CTAS - 1);
    }
    __syncthreads();
    if (s_last) {
        __threadfence();
        const float bv = bb[0];
        #pragma unroll
        for (int i = 0; i < B_ROWS / THREADS; i++) {
            int r = tid + i * THREADS;
            out[r] = tanhf(g_acc[r] + bv);
        }
        if (tid == 0) g_done = 0;   // self-reset for next graph replay
    }
}

// ---------------------------------------------------------------------------
extern "C" void kernel_launch(void* const* d_in, const int* in_sizes, int n_in,
                              void* d_out, int out_size) {
    const float* x      = (const float*)d_in[0];
    const float* ds     = (const float*)d_in[1];
    const float* labels = (const float*)d_in[2];
    const float* lam    = (const float*)d_in[3];
    const float* b      = (const float*)d_in[4];
    float* out = (float*)d_out;
    (void)in_sizes; (void)n_in; (void)out_size;

    cudaFuncSetAttribute(svm_main, cudaFuncAttributeMaxDynamicSharedMemorySize,
                         SMEM_BYTES);

    prep<<<(B_ROWS + N_PAD + 7) / 8, 256>>>(x, ds, labels, lam);

    dim3 grid(GRID_X, NSPLIT);
    svm_main<<<grid, THREADS, SMEM_BYTES>>>(x, ds, b, out);
}

// round 12
// speedup vs baseline: 3.5275x; 3.5275x over previous
#include <cuda_runtime.h>
#include <cuda_bf16.h>
#include <math.h>
#include <stdint.h>

// ---------------------------------------------------------------------------
// SVM RBF inference: out = tanh(K @ (labels*relu(lambda)) + b)
//   K[b,n] = exp(-(||x_b||^2+||s_n||^2-2 x_b.s_n)/2), B=2048, N=50000, D=256
// v11: R8 (best, 86.5us) with ONE change: the MMA opcode. Cross-round rate
//   data: f16-acc mma.sync saturates at 0.125 mma/cyc/SM on sm_103's legacy
//   tensor path (R5/R8/R9/R10 all pinned there); f32-acc bf16 mma reaches
//   0.234 (R1). Hypothesis: f16-acc form is half-rate (rt 32 vs 16 cyc/SMSP).
//   So: bf16 inputs + f32 accumulators, same augmented 64-wide screen.
//   Augmented screen: dims 0..61 raw bf16, dims 62/63 encode norms so the
//   f32 accumulator == -0.5*LB (LB = 62-dim sqdist, lower bound of 256-dim
//   sqdist; bf16 rounding costs <~1 on LB vs a >=25 margin). Skip when
//   LB >= 51 (skipped mass < 1e-9 vs tol 7.6e-4); rare candidates
//   (P~2-5e-4/pair, N(0,1) data) take an exact fp32 256-dim fixup from the
//   ORIGINAL inputs -> correct for any input. tanh finalize folded into the
//   last-arriving CTA. R11 lesson: s8 IMMA is ~1/8 rate on this path — dead.
// ---------------------------------------------------------------------------

#define B_ROWS   2048
#define D_DIM    256
#define D_H      64              // screening K (62 data dims + 2 aug)
#define N_ROWS   50000
#define N_PAD    50176           // 392 * 128
#define N_TILES  392
#define BM       128
#define BN       128
#define THREADS  256
#define NSPLIT   18
#define GRID_X   (B_ROWS / BM)
#define TOTAL_CTAS (GRID_X * NSPLIT)
#define TACC     (-25.5f)        // acc = -0.5*LB; rescan if acc > TACC

#define A_STRIDE 144             // 64 bf16 + 8 pad (9*16B: conflict-free LDSM)
#define A_BYTES  (BM * A_STRIDE) // 18432
#define B_STG    (BN * A_STRIDE) // 18432
#define NSTG     3
#define SMEM_BYTES (A_BYTES + NSTG * B_STG) // 73728 -> 2 CTAs/SM (147KB)

// Scratch (static device arrays: no allocation anywhere)
__device__ __align__(256) __nv_bfloat16 g_xh[B_ROWS * D_H];
__device__ __align__(256) __nv_bfloat16 g_sh[N_PAD * D_H];
__device__ __align__(256) float  g_w[N_PAD];
__device__ __align__(256) float  g_acc[B_ROWS];
__device__ int g_done;           // 0 at start of every call (self-resetting)

// ---------------------------------------------------------------------------
// Merged prep: one warp per row; builds augmented bf16 rows + w; zeroes acc.
// ---------------------------------------------------------------------------
__global__ void prep(const float* __restrict__ x,
                     const float* __restrict__ ds,
                     const float* __restrict__ labels,
                     const float* __restrict__ lam) {
    const int lane = threadIdx.x & 31;
    const int gw = blockIdx.x * 8 + (threadIdx.x >> 5);
    if (gw < B_ROWS) {
        const int row = gw;
        float2 v = reinterpret_cast<const float2*>(x + (size_t)row * D_DIM)[lane];
        // use the bf16-rounded values for the norm so acc == -0.5*LB exactly
        float bx = __bfloat162float(__float2bfloat16_rn(v.x));
        float by = __bfloat162float(__float2bfloat16_rn(v.y));
        float ss = (lane < 31) ? (bx * bx + by * by) : 0.0f;
        #pragma unroll
        for (int o = 16; o > 0; o >>= 1) ss += __shfl_xor_sync(0xffffffffu, ss, o);
        __nv_bfloat162 out = (lane < 31)
            ? __float22bfloat162_rn(v)
            : __float22bfloat162_rn(make_float2(-0.5f * ss, 1.0f));
        reinterpret_cast<__nv_bfloat162*>(g_xh + (size_t)row * D_H)[lane] = out;
        if (lane == 0) g_acc[row] = 0.0f;
    } else {
        const int row = gw - B_ROWS;
        if (row >= N_PAD) return;
        if (row < N_ROWS) {
            float2 v = reinterpret_cast<const float2*>(ds + (size_t)row * D_DIM)[lane];
            float bx = __bfloat162float(__float2bfloat16_rn(v.x));
            float by = __bfloat162float(__float2bfloat16_rn(v.y));
            float ss = (lane < 31) ? (bx * bx + by * by) : 0.0f;
            #pragma unroll
            for (int o = 16; o > 0; o >>= 1) ss += __shfl_xor_sync(0xffffffffu, ss, o);
            __nv_bfloat162 out = (lane < 31)
                ? __float22bfloat162_rn(v)
                : __float22bfloat162_rn(make_float2(1.0f, -0.5f * ss));
            reinterpret_cast<__nv_bfloat162*>(g_sh + (size_t)row * D_H)[lane] = out;
            if (lane == 0) g_w[row] = labels[row] * fmaxf(lam[row], 0.0f);
        } else {
            __nv_bfloat162 out = (lane < 31)
                ? __float22bfloat162_rn(make_float2(0.0f, 0.0f))
                : __float22bfloat162_rn(make_float2(1.0f, -30000.0f));
            reinterpret_cast<__nv_bfloat162*>(g_sh + (size_t)row * D_H)[lane] = out;
            if (lane == 0) g_w[row] = 0.0f;
        }
    }
}

// ---------------------------------------------------------------------------
// PTX helpers
// ---------------------------------------------------------------------------
__device__ __forceinline__ void cp16(uint32_t saddr, const void* gaddr) {
    asm volatile("cp.async.cg.shared.global [%0], [%1], 16;\n"
                 :: "r"(saddr), "l"(gaddr));
}
__device__ __forceinline__ void cp_commit() {
    asm volatile("cp.async.commit_group;\n");
}
template <int N>
__device__ __forceinline__ void cp_wait() {
    asm volatile("cp.async.wait_group %0;\n" :: "n"(N));
}
__device__ __forceinline__ void ldsm4(uint32_t* r, uint32_t addr) {
    asm volatile("ldmatrix.sync.aligned.m8n8.x4.shared.b16 {%0,%1,%2,%3}, [%4];"
                 : "=r"(r[0]), "=r"(r[1]), "=r"(r[2]), "=r"(r[3]) : "r"(addr));
}
// bf16 in, f32 acc (the R1 opcode -- 2x issue rate vs f16-acc on sm_103)
__device__ __forceinline__ void mma_bf16(float d[4], const uint32_t a[4],
                                         uint32_t b0, uint32_t b1) {
    asm volatile(
        "mma.sync.aligned.m16n8k16.row.col.f32.bf16.bf16.f32 "
        "{%0,%1,%2,%3},{%4,%5,%6,%7},{%8,%9},{%0,%1,%2,%3};"
        : "+f"(d[0]), "+f"(d[1]), "+f"(d[2]), "+f"(d[3])
        : "r"(a[0]), "r"(a[1]), "r"(a[2]), "r"(a[3]), "r"(b0), "r"(b1));
}

// Cold path: exact 256-dim fp32 squared distance from the ORIGINAL inputs.
__device__ __noinline__ float exact_sqdist(const float* __restrict__ xr,
                                           const float* __restrict__ sr) {
    float d2 = 0.0f;
    #pragma unroll 1
    for (int i = 0; i < D_DIM / 4; i++) {
        float4 a = reinterpret_cast<const float4*>(xr)[i];
        float4 b = reinterpret_cast<const float4*>(sr)[i];
        float dx = a.x - b.x, dy = a.y - b.y, dz = a.z - b.z, dw = a.w - b.w;
        d2 += dx * dx + dy * dy + dz * dz + dw * dw;
    }
    return d2;
}

// ---------------------------------------------------------------------------
// Main fused kernel (GEMM + screening epilogue + folded tanh finalize)
//   8 warps: wm = wid&3 (M, 32 rows), wn = wid>>2 (N, 64 cols)
// f32 acc layout (m16n8k16): reg r of lane l ->
//   row = (l>>2) + 8*(r>>1), col = 2*(l&3) + (r&1)
// ---------------------------------------------------------------------------
__global__ void __launch_bounds__(THREADS, 2)
svm_main(const float* __restrict__ xp, const float* __restrict__ sp,
         const float* __restrict__ bb, float* __restrict__ out) {
    extern __shared__ char smem[];
    uint32_t smem_u;
    asm("{ .reg .u64 t; cvta.to.shared.u64 t, %1; cvt.u32.u64 %0, t; }"
        : "=r"(smem_u) : "l"(smem));
    const uint32_t sA = smem_u;
    const uint32_t sB = smem_u + A_BYTES;

    const int tid  = threadIdx.x;
    const int lane = tid & 31;
    const int wid  = tid >> 5;
    const int wm   = wid & 3;   // 4 warps along M (32 rows each)
    const int wn   = wid >> 2;  // 2 warps along N (64 cols each)
    const int bm0  = blockIdx.x * BM;
    const int split = blockIdx.y;

    // ---- A tile load (128 rows x 64 bf16), resident ----
    {
        const __nv_bfloat16* gx = g_xh + (size_t)bm0 * D_H;
        #pragma unroll
        for (int i = 0; i < 4; i++) {
            int u = tid + THREADS * i;      // 0..1023 16B chunks
            int r = u >> 3, c = u & 7;
            cp16(sA + r * A_STRIDE + c * 16, gx + (size_t)r * D_H + c * 8);
        }
        cp_commit();                        // GA
    }

    auto load_b = [&](int buf, int t0) {
        const __nv_bfloat16* gs = g_sh + (size_t)t0 * BN * D_H;
        const uint32_t base = sB + buf * B_STG;
        #pragma unroll
        for (int i = 0; i < 4; i++) {
            int u = tid + THREADS * i;
            int r = u >> 3, c = u & 7;
            cp16(base + r * A_STRIDE + c * 16, gs + (size_t)r * D_H + c * 8);
        }
    };

    const int ntiles = (N_TILES - split + NSPLIT - 1) / NSPLIT;
    load_b(0, split); cp_commit();          // G0
    if (ntiles > 1) load_b(1, split + NSPLIT);
    cp_commit();                            // G1 (possibly empty)

    // ---- hoisted LDSM addresses ----
    uint32_t a_base[2];
    #pragma unroll
    for (int mi = 0; mi < 2; mi++) {
        int r = wm * 32 + mi * 16 + (lane & 15);
        a_base[mi] = sA + r * A_STRIDE + (lane >> 4) * 16;
    }
    uint32_t b_row[4];
    {
        int grp = lane >> 3;
        #pragma unroll
        for (int p = 0; p < 4; p++) {
            int r = wn * 64 + p * 16 + (grp >> 1) * 8 + (lane & 7);
            b_row[p] = (uint32_t)(r * A_STRIDE + (grp & 1) * 16);
        }
    }

    float rsum[2][2] = {{0.0f, 0.0f}, {0.0f, 0.0f}};

    int t = split;
    for (int ti = 0; ti < ntiles; ti++, t += NSPLIT) {
        cp_wait<1>();            // tile ti's group complete (ti+1 in flight)
        __syncthreads();         // single barrier: also protects stage (ti+2)%3
                                 // (last read at tile ti-1) before refill below

        if (ti + 2 < ntiles) load_b((ti + 2) % NSTG, t + 2 * NSPLIT);
        cp_commit();             // always commit (keeps wait<1> exact)

        const uint32_t stg = sB + (ti % NSTG) * B_STG;

        float acc[2][8][4];
        #pragma unroll
        for (int mi = 0; mi < 2; mi++)
            #pragma unroll
            for (int ni = 0; ni < 8; ni++)
                #pragma unroll
                for (int r = 0; r < 4; r++) acc[mi][ni][r] = 0.0f;

        #pragma unroll
        for (int j = 0; j < 4; j++) {        // 4 k16 steps over D_H=64
            // batch 6 independent LDSMs (2 A + 4 B) -> MLP 6 (R5-proven)
            uint32_t a[2][4], bq[4][4];
            ldsm4(a[0], a_base[0] + j * 32);
            ldsm4(a[1], a_base[1] + j * 32);
            #pragma unroll
            for (int p = 0; p < 4; p++)
                ldsm4(bq[p], stg + b_row[p] + j * 32);
            // 16 MMAs (f32 acc)
            #pragma unroll
            for (int p = 0; p < 4; p++) {
                mma_bf16(acc[0][2 * p],     a[0], bq[p][0], bq[p][1]);
                mma_bf16(acc[0][2 * p + 1], a[0], bq[p][2], bq[p][3]);
                mma_bf16(acc[1][2 * p],     a[1], bq[p][0], bq[p][1]);
                mma_bf16(acc[1][2 * p + 1], a[1], bq[p][2], bq[p][3]);
            }
        }

        // ---- epilogue: acc == -0.5*LB; FMAX tree screen, cold exact fixup ----
        const int n0 = t * BN;
        #pragma unroll
        for (int mi = 0; mi < 2; mi++) {
            #pragma unroll
            for (int h = 0; h < 2; h++) {
                const int h2 = 2 * h;
                float mx = acc[mi][0][h2];
                #pragma unroll
                for (int ni = 0; ni < 8; ni++) {
                    mx = fmaxf(mx, acc[mi][ni][h2]);
                    mx = fmaxf(mx, acc[mi][ni][h2 + 1]);
                }
                if (__builtin_expect(mx > TACC, 0)) {
                    const int row = bm0 + wm * 32 + mi * 16 + (lane >> 2) + 8 * h;
                    const float* xr = xp + (size_t)row * D_DIM;
                    #pragma unroll
                    for (int ni = 0; ni < 8; ni++) {
                        #pragma unroll
                        for (int par = 0; par < 2; par++) {
                            float v = acc[mi][ni][h2 + par];
                            const int col = n0 + wn * 64 + ni * 8 + 2 * (lane & 3) + par;
                            if (v > TACC && col < N_ROWS) {
                                float d2 = exact_sqdist(xr, sp + (size_t)col * D_DIM);
                                rsum[mi][h] += __expf(-0.5f * d2) * g_w[col];
                            }
                        }
                    }
                }
            }
        }
    }

    // ---- row reduction: shfl within quad, one atomic per row per CTA ----
    #pragma unroll
    for (int mi = 0; mi < 2; mi++) {
        #pragma unroll
        for (int h = 0; h < 2; h++) {
            float v = rsum[mi][h];
            v += __shfl_xor_sync(0xffffffffu, v, 1);
            v += __shfl_xor_sync(0xffffffffu, v, 2);
            if ((lane & 3) == 0) {
                int r = bm0 + wm * 32 + mi * 16 + (lane >> 2) + h * 8;
                atomicAdd(&g_acc[r], v);
            }
        }
    }

    // ---- folded finalize: last CTA applies tanh(acc + b) ----
    __shared__ int s_last;
    __threadfence();
    __syncthreads();
    if (tid == 0) {
        int old = atomicAdd(&g_done, 1);
        s_last = (old == TOTAL_CTAS - 1);
    }
    __syncthreads();
    if (s_last) {
        __threadfence();
        const float bv = bb[0];
        #pragma unroll
        for (int i = 0; i < B_ROWS / THREADS; i++) {
            int r = tid + i * THREADS;
            out[r] = tanhf(g_acc[r] + bv);
        }
        if (tid == 0) g_done = 0;   // self-reset for next graph replay
    }
}

// ---------------------------------------------------------------------------
extern "C" void kernel_launch(void* const* d_in, const int* in_sizes, int n_in,
                              void* d_out, int out_size) {
    const float* x      = (const float*)d_in[0];
    const float* ds     = (const float*)d_in[1];
    const float* labels = (const float*)d_in[2];
    const float* lam    = (const float*)d_in[3];
    const float* b      = (const float*)d_in[4];
    float* out = (float*)d_out;
    (void)in_sizes; (void)n_in; (void)out_size;

    cudaFuncSetAttribute(svm_main, cudaFuncAttributeMaxDynamicSharedMemorySize,
                         SMEM_BYTES);

    prep<<<(B_ROWS + N_PAD + 7) / 8, 256>>>(x, ds, labels, lam);

    dim3 grid(GRID_X, NSPLIT);
    svm_main<<<grid, THREADS, SMEM_BYTES>>>(x, ds, b, out);
}